// round 14
// baseline (speedup 1.0000x reference)
#include <cuda_runtime.h>
#include <cuda_bf16.h>
#include <math.h>

// Problem constants (from reference): N_CUTS=4e6, DIM=64, N_CLUSTERS=50, N_VARIANTS=2000
#define DIM 64
#define MAX_SEG 100000
#define MAX_CLUSTERS 64

// Scratch (static: allocation-free rule)
__device__ float g_raw[(size_t)MAX_SEG * DIM];    // raw segment sums, 25.6 MB

// Fast log1p for |x| small (here |x| <~ 0.01 always): 5-term Taylor, error
// x^6/6 (< 3e-9 relative even at x=0.05). Guarded fallback for robustness.
__device__ __forceinline__ float log1p_fast(float x) {
    if (fabsf(x) > 0.1f) return log1pf(x);
    return x * (1.f - x * (0.5f - x * (0.33333333f - x * (0.25f - x * 0.2f))));
}

// Per-warp indptr dtype check (1 load per lane for lanes 0..15; L2-hot).
// int64 values here are << 2^31 -> all odd 32-bit words zero; int32 odd words
// are sorted random breakpoints (essentially never all zero).
__device__ __forceinline__ bool indptr_is_64_warp(const int* __restrict__ ipw, int lane) {
    int w = (lane < 16) ? __ldg(&ipw[2 * lane + 1]) : 0;
    return __ballot_sync(0xffffffffu, w != 0) == 0u;
}

// ---------------------------------------------------------------------------
// Kernel 1 (FROZEN, R9-proven: 161 us @ 82% DRAM): CSR segment sum.
// One CTA per segment; 128 threads = 8 row-groups x 16 float4 lanes; 32-bit
// trip counter + pointer increment; shfl half-combine + one-sync smem add.
// ---------------------------------------------------------------------------
__global__ void __launch_bounds__(128) seg_sum_kernel(
    const float4* __restrict__ emb,   // [n_cuts * 16] float4 (row = 16 float4)
    const int* __restrict__ ipw,      // indptr as 32-bit words
    float* __restrict__ raw)          // [n_seg * 64]
{
    const int s = blockIdx.x;
    const int tid = threadIdx.x;
    const int lane = tid & 31;

    int r0, r1;  // row indices < 4M: always fit in int32
    if (indptr_is_64_warp(ipw, lane)) {
        const long long* ip = (const long long*)ipw;
        r0 = (int)__ldg(&ip[s]); r1 = (int)__ldg(&ip[s + 1]);
    } else {
        r0 = __ldg(&ipw[s]); r1 = __ldg(&ipw[s + 1]);
    }

    const int q = tid & 15;   // float4 index within a row (0..15)
    const int g = tid >> 4;   // row group (0..7)

    float ax = 0.f, ay = 0.f, az = 0.f, aw = 0.f;
    {
        const float4* p = emb + (size_t)(r0 + g) * 16 + q;
        int n = r1 - (r0 + g);            // remaining rows for this group
        for (; n > 0; n -= 8, p += 128) { // stride 8 rows = 2KB
            float4 v = __ldg(p);
            ax += v.x; ay += v.y; az += v.z; aw += v.w;
        }
    }

    ax += __shfl_down_sync(0xffffffffu, ax, 16);
    ay += __shfl_down_sync(0xffffffffu, ay, 16);
    az += __shfl_down_sync(0xffffffffu, az, 16);
    aw += __shfl_down_sync(0xffffffffu, aw, 16);

    __shared__ float4 sm[4][16];
    const int w = tid >> 5;
    if (lane < 16) sm[w][lane] = make_float4(ax, ay, az, aw);
    __syncthreads();

    if (tid < 16) {
        float4 a = sm[0][tid], b = sm[1][tid], c = sm[2][tid], d = sm[3][tid];
        float4 r = make_float4(a.x + b.x + c.x + d.x,
                               a.y + b.y + c.y + d.y,
                               a.z + b.z + c.z + d.z,
                               a.w + b.w + c.w + d.w);
        ((float4*)(raw + (size_t)s * DIM))[tid] = r;
    }
}

// ---------------------------------------------------------------------------
// Kernel 2 (warp-split, NC even): fused stats+apply with the cluster axis
// split 2-way INSIDE each warp (R12 lesson: a block barrier between load and
// store phases kills this kernel; __shfl_xor is warp-internal = free).
//   lane 0..15  -> clusters [0, NC/2)  of columns warpbase + 0..15
//   lane 16..31 -> clusters [NC/2, NC) of the same 16 columns
// Each thread holds NC/2 y-values in registers; one load + one log1p per
// element; partial (sum, ssq) combined via shfl_xor(16); no barriers after
// init. 256k threads -> ~2x latency hiding vs R13's 128k.
// Stats on UNSHIFTED y = log1p(raw/lib) (shift-invariance avoids the fp32
// cancellation the -2 offset would cause; std ~ 6e-5 vs values ~ 2).
//   out[c,v,d]    = y - 2
//   out[c,v,64+d] = (y - mean)/(std_ddof1 + 1e-5)
// ---------------------------------------------------------------------------
template <int NC>
__global__ void __launch_bounds__(128) finalize_warp_kernel(
    const float* __restrict__ raw,   // [NC * n_variants * 64]
    const float* __restrict__ lib,   // [NC]
    float* __restrict__ out,         // [NC * n_variants * 128]
    int n_variants)
{
    constexpr int H = NC / 2;
    __shared__ float s_inv[NC];
    if (threadIdx.x < NC) s_inv[threadIdx.x] = 1.f / lib[threadIdx.x];
    __syncthreads();   // only orders s_inv init (before load phase)

    const int lane = threadIdx.x & 31;
    const int wid  = threadIdx.x >> 5;
    const int half = lane >> 4;               // 0 or 1
    const int slot = lane & 15;
    const int col  = blockIdx.x * 64 + wid * 16 + slot;  // v*64 + d
    const int total = n_variants * DIM;       // cluster stride in raw
    const bool live = (col < total);
    const int c0 = half * H;

    float y[H];
    float sum = 0.f, ssq = 0.f;
    {
        const float* p = raw + (size_t)c0 * total + col;
        #pragma unroll
        for (int c = 0; c < H; ++c) {
            float t = live ? log1p_fast(__ldg(p) * s_inv[c0 + c]) : 0.f;
            p += total;
            y[c] = t;
            sum += t;
            ssq = fmaf(t, t, ssq);
        }
    }

    // combine the two cluster-halves of this column (warp-internal, no barrier)
    sum += __shfl_xor_sync(0xffffffffu, sum, 16);
    ssq += __shfl_xor_sync(0xffffffffu, ssq, 16);

    const float meanY = sum / (float)NC;
    const float var = (ssq - sum * meanY) / (float)(NC - 1);
    const float idn = 1.f / (sqrtf(fmaxf(var, 0.f)) + 1e-5f);

    if (live) {
        const int v = col >> 6;
        const int d = col & 63;
        const size_t ostride = (size_t)n_variants * (2 * DIM);
        float* o = out + (size_t)c0 * ostride + (size_t)v * (2 * DIM) + d;
        #pragma unroll
        for (int c = 0; c < H; ++c) {
            o[0]   = y[c] - 2.0f;
            o[DIM] = (y[c] - meanY) * idn;
            o += ostride;
        }
    }
}

// Generic fallback (R6-proven two-pass form) for n_clusters != 50.
__global__ void __launch_bounds__(128) finalize_gen_kernel(
    const float* __restrict__ raw,
    const float* __restrict__ lib,
    float* __restrict__ out,
    int n_clusters, int n_variants)
{
    __shared__ float s_inv[MAX_CLUSTERS];
    if (threadIdx.x < n_clusters && threadIdx.x < MAX_CLUSTERS)
        s_inv[threadIdx.x] = 1.f / lib[threadIdx.x];
    __syncthreads();

    const int idx = blockIdx.x * blockDim.x + threadIdx.x;
    const int total = n_variants * DIM;
    if (idx >= total) return;

    const float* p = raw + idx;
    float sum = 0.f, ssq = 0.f;
    for (int c = 0; c < n_clusters; ++c) {
        float yv = log1p_fast(__ldg(p) * s_inv[c]);
        p += total;
        sum += yv;
        ssq = fmaf(yv, yv, ssq);
    }
    const float meanY = sum / (float)n_clusters;
    const float var = (ssq - sum * meanY) / (float)(n_clusters - 1);
    const float idn = 1.f / (sqrtf(fmaxf(var, 0.f)) + 1e-5f);

    const int v = idx >> 6;
    const int d = idx & 63;
    const float* p2 = raw + idx;
    float* o = out + (size_t)v * (2 * DIM) + d;
    const size_t ostride = (size_t)n_variants * (2 * DIM);
    for (int c = 0; c < n_clusters; ++c) {
        float yv = log1p_fast(__ldg(p2) * s_inv[c]);
        p2 += total;
        o[0]   = yv - 2.0f;
        o[DIM] = (yv - meanY) * idn;
        o += ostride;
    }
}

extern "C" void kernel_launch(void* const* d_in, const int* in_sizes, int n_in,
                              void* d_out, int out_size)
{
    const float* emb    = (const float*)d_in[0];   // [n_cuts, 64] fp32
    const float* lib    = (const float*)d_in[1];   // [n_clusters] fp32
    const int*   indptr = (const int*)d_in[2];     // [n_seg + 1] int32 OR int64 words

    const int n_clusters = in_sizes[1];
    const int n_seg      = in_sizes[2] - 1;
    const int n_variants = n_seg / n_clusters;

    float* raw;
    cudaGetSymbolAddress((void**)&raw, g_raw);

    // Kernel 1: one block per segment
    seg_sum_kernel<<<n_seg, 128>>>((const float4*)emb, indptr, raw);

    // Kernel 2: fused stats+apply
    const int total_vd = n_variants * DIM;
    if (n_clusters == 50) {
        // 64 columns per 128-thread block (each warp: 16 cols x 2 halves)
        const int blocks2 = (total_vd + 63) / 64;
        finalize_warp_kernel<50><<<blocks2, 128>>>(raw, lib, (float*)d_out,
                                                   n_variants);
    } else {
        const int blocks2 = (total_vd + 127) / 128;
        finalize_gen_kernel<<<blocks2, 128>>>(raw, lib, (float*)d_out,
                                              n_clusters, n_variants);
    }
}

// round 15
// speedup vs baseline: 1.1088x; 1.1088x over previous
#include <cuda_runtime.h>
#include <cuda_bf16.h>
#include <math.h>

// Problem constants (from reference): N_CUTS=4e6, DIM=64, N_CLUSTERS=50, N_VARIANTS=2000
#define DIM 64
#define MAX_SEG 100000
#define MAX_CLUSTERS 64

// Scratch (static: allocation-free rule)
__device__ float g_raw[(size_t)MAX_SEG * DIM];    // raw segment sums, 25.6 MB

// Fast log1p for |x| small (here |x| <~ 0.01 always): 5-term Taylor, error
// x^6/6 (< 3e-9 relative even at x=0.05). Guarded fallback for robustness.
__device__ __forceinline__ float log1p_fast(float x) {
    if (fabsf(x) > 0.1f) return log1pf(x);
    return x * (1.f - x * (0.5f - x * (0.33333333f - x * (0.25f - x * 0.2f))));
}

// Per-warp indptr dtype check (1 load per lane for lanes 0..15; L2-hot).
// int64 values here are << 2^31 -> all odd 32-bit words zero; int32 odd words
// are sorted random breakpoints (essentially never all zero).
__device__ __forceinline__ bool indptr_is_64_warp(const int* __restrict__ ipw, int lane) {
    int w = (lane < 16) ? __ldg(&ipw[2 * lane + 1]) : 0;
    return __ballot_sync(0xffffffffu, w != 0) == 0u;
}

// ---------------------------------------------------------------------------
// Kernel 1 (FROZEN, R9-proven: 161 us @ 82% DRAM): CSR segment sum.
// One CTA per segment; 128 threads = 8 row-groups x 16 float4 lanes; 32-bit
// trip counter + pointer increment; shfl half-combine + one-sync smem add.
// ---------------------------------------------------------------------------
__global__ void __launch_bounds__(128) seg_sum_kernel(
    const float4* __restrict__ emb,   // [n_cuts * 16] float4 (row = 16 float4)
    const int* __restrict__ ipw,      // indptr as 32-bit words
    float* __restrict__ raw)          // [n_seg * 64]
{
    const int s = blockIdx.x;
    const int tid = threadIdx.x;
    const int lane = tid & 31;

    int r0, r1;  // row indices < 4M: always fit in int32
    if (indptr_is_64_warp(ipw, lane)) {
        const long long* ip = (const long long*)ipw;
        r0 = (int)__ldg(&ip[s]); r1 = (int)__ldg(&ip[s + 1]);
    } else {
        r0 = __ldg(&ipw[s]); r1 = __ldg(&ipw[s + 1]);
    }

    const int q = tid & 15;   // float4 index within a row (0..15)
    const int g = tid >> 4;   // row group (0..7)

    float ax = 0.f, ay = 0.f, az = 0.f, aw = 0.f;
    {
        const float4* p = emb + (size_t)(r0 + g) * 16 + q;
        int n = r1 - (r0 + g);            // remaining rows for this group
        for (; n > 0; n -= 8, p += 128) { // stride 8 rows = 2KB
            float4 v = __ldg(p);
            ax += v.x; ay += v.y; az += v.z; aw += v.w;
        }
    }

    ax += __shfl_down_sync(0xffffffffu, ax, 16);
    ay += __shfl_down_sync(0xffffffffu, ay, 16);
    az += __shfl_down_sync(0xffffffffu, az, 16);
    aw += __shfl_down_sync(0xffffffffu, aw, 16);

    __shared__ float4 sm[4][16];
    const int w = tid >> 5;
    if (lane < 16) sm[w][lane] = make_float4(ax, ay, az, aw);
    __syncthreads();

    if (tid < 16) {
        float4 a = sm[0][tid], b = sm[1][tid], c = sm[2][tid], d = sm[3][tid];
        float4 r = make_float4(a.x + b.x + c.x + d.x,
                               a.y + b.y + c.y + d.y,
                               a.z + b.z + c.z + d.z,
                               a.w + b.w + c.w + d.w);
        ((float4*)(raw + (size_t)s * DIM))[tid] = r;
    }
}

// ---------------------------------------------------------------------------
// Kernel 2 (R13-proven register version, 128-thr blocks; + streaming cache
// hints). Each thread owns one (v,d) column: all 50 y-values in registers,
// ONE load + ONE log1p per element, no inter-thread coupling (R12/R14 lesson:
// any cluster-axis split halves warp store segments to 64B and doubles
// transactions — conclusively worse).
// Cache policy: raw elements are read exactly once -> __ldcs (evict-first);
// out is never re-read -> __stcs, so the 51.2MB store stream doesn't evict
// the L2-resident raw (25.6MB) mid-kernel.
// Stats on UNSHIFTED y = log1p(raw/lib) (shift-invariance avoids the fp32
// cancellation the -2 offset would cause; std ~ 6e-5 vs values ~ 2).
//   out[c,v,d]    = y - 2
//   out[c,v,64+d] = (y - mean)/(std_ddof1 + 1e-5)
// ---------------------------------------------------------------------------
template <int NC>
__global__ void __launch_bounds__(128) finalize_reg_kernel(
    const float* __restrict__ raw,   // [NC * n_variants * 64]
    const float* __restrict__ lib,   // [NC]
    float* __restrict__ out,         // [NC * n_variants * 128]
    int n_variants)
{
    __shared__ float s_inv[NC];
    if (threadIdx.x < NC) s_inv[threadIdx.x] = 1.f / lib[threadIdx.x];
    __syncthreads();

    const int idx = blockIdx.x * blockDim.x + threadIdx.x; // v*64 + d
    const int total = n_variants * DIM;                    // cluster stride in raw
    if (idx >= total) return;

    float y[NC];
    float sum = 0.f, ssq = 0.f;
    {
        const float* p = raw + idx;
        #pragma unroll
        for (int c = 0; c < NC; ++c) {
            float t = log1p_fast(__ldcs(p) * s_inv[c]);
            p += total;
            y[c] = t;
            sum += t;
            ssq = fmaf(t, t, ssq);
        }
    }

    const float meanY = sum / (float)NC;
    const float var = (ssq - sum * meanY) / (float)(NC - 1);
    const float idn = 1.f / (sqrtf(fmaxf(var, 0.f)) + 1e-5f);

    const int v = idx >> 6;
    const int d = idx & 63;
    float* o = out + (size_t)v * (2 * DIM) + d;   // (c*nv + v)*128 + d
    const size_t ostride = (size_t)n_variants * (2 * DIM);
    #pragma unroll
    for (int c = 0; c < NC; ++c) {
        __stcs(o, y[c] - 2.0f);
        __stcs(o + DIM, (y[c] - meanY) * idn);
        o += ostride;
    }
}

// Generic fallback (R6-proven two-pass form) for n_clusters != 50.
__global__ void __launch_bounds__(128) finalize_gen_kernel(
    const float* __restrict__ raw,
    const float* __restrict__ lib,
    float* __restrict__ out,
    int n_clusters, int n_variants)
{
    __shared__ float s_inv[MAX_CLUSTERS];
    if (threadIdx.x < n_clusters && threadIdx.x < MAX_CLUSTERS)
        s_inv[threadIdx.x] = 1.f / lib[threadIdx.x];
    __syncthreads();

    const int idx = blockIdx.x * blockDim.x + threadIdx.x;
    const int total = n_variants * DIM;
    if (idx >= total) return;

    const float* p = raw + idx;
    float sum = 0.f, ssq = 0.f;
    for (int c = 0; c < n_clusters; ++c) {
        float yv = log1p_fast(__ldg(p) * s_inv[c]);
        p += total;
        sum += yv;
        ssq = fmaf(yv, yv, ssq);
    }
    const float meanY = sum / (float)n_clusters;
    const float var = (ssq - sum * meanY) / (float)(n_clusters - 1);
    const float idn = 1.f / (sqrtf(fmaxf(var, 0.f)) + 1e-5f);

    const int v = idx >> 6;
    const int d = idx & 63;
    const float* p2 = raw + idx;
    float* o = out + (size_t)v * (2 * DIM) + d;
    const size_t ostride = (size_t)n_variants * (2 * DIM);
    for (int c = 0; c < n_clusters; ++c) {
        float yv = log1p_fast(__ldg(p2) * s_inv[c]);
        p2 += total;
        o[0]   = yv - 2.0f;
        o[DIM] = (yv - meanY) * idn;
        o += ostride;
    }
}

extern "C" void kernel_launch(void* const* d_in, const int* in_sizes, int n_in,
                              void* d_out, int out_size)
{
    const float* emb    = (const float*)d_in[0];   // [n_cuts, 64] fp32
    const float* lib    = (const float*)d_in[1];   // [n_clusters] fp32
    const int*   indptr = (const int*)d_in[2];     // [n_seg + 1] int32 OR int64 words

    const int n_clusters = in_sizes[1];
    const int n_seg      = in_sizes[2] - 1;
    const int n_variants = n_seg / n_clusters;

    float* raw;
    cudaGetSymbolAddress((void**)&raw, g_raw);

    // Kernel 1: one block per segment
    seg_sum_kernel<<<n_seg, 128>>>((const float4*)emb, indptr, raw);

    // Kernel 2: fused stats+apply, one thread per (variant, dim), 128-thr blocks
    const int total_vd = n_variants * DIM;
    const int blocks2 = (total_vd + 127) / 128;
    if (n_clusters == 50) {
        finalize_reg_kernel<50><<<blocks2, 128>>>(raw, lib, (float*)d_out,
                                                  n_variants);
    } else {
        finalize_gen_kernel<<<blocks2, 128>>>(raw, lib, (float*)d_out,
                                              n_clusters, n_variants);
    }
}

// round 16
// speedup vs baseline: 1.1503x; 1.0375x over previous
#include <cuda_runtime.h>
#include <cuda_bf16.h>
#include <math.h>

// Problem constants (from reference): N_CUTS=4e6, DIM=64, N_CLUSTERS=50, N_VARIANTS=2000
#define DIM 64
#define MAX_SEG 100000
#define MAX_CLUSTERS 64

// Scratch (static: allocation-free rule)
__device__ float g_raw[(size_t)MAX_SEG * DIM];    // raw segment sums, 25.6 MB

// Fast log1p for |x| small (here |x| <~ 0.01 always): 5-term Taylor, error
// x^6/6 (< 3e-9 relative even at x=0.05). Guarded fallback for robustness.
__device__ __forceinline__ float log1p_fast(float x) {
    if (fabsf(x) > 0.1f) return log1pf(x);
    return x * (1.f - x * (0.5f - x * (0.33333333f - x * (0.25f - x * 0.2f))));
}

// Per-warp indptr dtype check (1 load per lane for lanes 0..15; L2-hot).
// int64 values here are << 2^31 -> all odd 32-bit words zero; int32 odd words
// are sorted random breakpoints (essentially never all zero).
__device__ __forceinline__ bool indptr_is_64_warp(const int* __restrict__ ipw, int lane) {
    int w = (lane < 16) ? __ldg(&ipw[2 * lane + 1]) : 0;
    return __ballot_sync(0xffffffffu, w != 0) == 0u;
}

// evict-first float4 load: each emb line is touched exactly once, so caching
// it in L2 only evicts the raw lines finalize needs.
__device__ __forceinline__ float4 ldcs4(const float4* p) {
    float4 v;
    asm volatile("ld.global.cs.v4.f32 {%0,%1,%2,%3}, [%4];"
                 : "=f"(v.x), "=f"(v.y), "=f"(v.z), "=f"(v.w) : "l"(p));
    return v;
}

// ---------------------------------------------------------------------------
// Kernel 1 (R9 structure, frozen; + __ldcs on emb): CSR segment sum.
// One CTA per segment; 128 threads = 8 row-groups x 16 float4 lanes; 32-bit
// trip counter + pointer increment; shfl half-combine + one-sync smem add.
// emb loads are evict-first so the 1GB stream doesn't evict raw from L2
// (raw is re-read by finalize immediately after).
// ---------------------------------------------------------------------------
__global__ void __launch_bounds__(128) seg_sum_kernel(
    const float4* __restrict__ emb,   // [n_cuts * 16] float4 (row = 16 float4)
    const int* __restrict__ ipw,      // indptr as 32-bit words
    float* __restrict__ raw)          // [n_seg * 64]
{
    const int s = blockIdx.x;
    const int tid = threadIdx.x;
    const int lane = tid & 31;

    int r0, r1;  // row indices < 4M: always fit in int32
    if (indptr_is_64_warp(ipw, lane)) {
        const long long* ip = (const long long*)ipw;
        r0 = (int)__ldg(&ip[s]); r1 = (int)__ldg(&ip[s + 1]);
    } else {
        r0 = __ldg(&ipw[s]); r1 = __ldg(&ipw[s + 1]);
    }

    const int q = tid & 15;   // float4 index within a row (0..15)
    const int g = tid >> 4;   // row group (0..7)

    float ax = 0.f, ay = 0.f, az = 0.f, aw = 0.f;
    {
        const float4* p = emb + (size_t)(r0 + g) * 16 + q;
        int n = r1 - (r0 + g);            // remaining rows for this group
        for (; n > 0; n -= 8, p += 128) { // stride 8 rows = 2KB
            float4 v = ldcs4(p);
            ax += v.x; ay += v.y; az += v.z; aw += v.w;
        }
    }

    ax += __shfl_down_sync(0xffffffffu, ax, 16);
    ay += __shfl_down_sync(0xffffffffu, ay, 16);
    az += __shfl_down_sync(0xffffffffu, az, 16);
    aw += __shfl_down_sync(0xffffffffu, aw, 16);

    __shared__ float4 sm[4][16];
    const int w = tid >> 5;
    if (lane < 16) sm[w][lane] = make_float4(ax, ay, az, aw);
    __syncthreads();

    if (tid < 16) {
        float4 a = sm[0][tid], b = sm[1][tid], c = sm[2][tid], d = sm[3][tid];
        float4 r = make_float4(a.x + b.x + c.x + d.x,
                               a.y + b.y + c.y + d.y,
                               a.z + b.z + c.z + d.z,
                               a.w + b.w + c.w + d.w);
        ((float4*)(raw + (size_t)s * DIM))[tid] = r;
    }
}

// ---------------------------------------------------------------------------
// Kernel 2 (R13-proven register version, 128-thr blocks). Each thread owns
// one (v,d) column: all 50 y-values in registers, ONE load + ONE log1p per
// element, no inter-thread coupling (R12/R14: any cluster-axis split halves
// warp store segments to 64B and doubles transactions — conclusively worse).
// out stores are evict-first (never re-read); raw reads use the normal path
// (want L2 hits, now more likely with emb marked streaming in kernel 1).
// Stats on UNSHIFTED y = log1p(raw/lib) (shift-invariance avoids the fp32
// cancellation the -2 offset would cause; std ~ 6e-5 vs values ~ 2).
//   out[c,v,d]    = y - 2
//   out[c,v,64+d] = (y - mean)/(std_ddof1 + 1e-5)
// ---------------------------------------------------------------------------
template <int NC>
__global__ void __launch_bounds__(128) finalize_reg_kernel(
    const float* __restrict__ raw,   // [NC * n_variants * 64]
    const float* __restrict__ lib,   // [NC]
    float* __restrict__ out,         // [NC * n_variants * 128]
    int n_variants)
{
    __shared__ float s_inv[NC];
    if (threadIdx.x < NC) s_inv[threadIdx.x] = 1.f / lib[threadIdx.x];
    __syncthreads();

    const int idx = blockIdx.x * blockDim.x + threadIdx.x; // v*64 + d
    const int total = n_variants * DIM;                    // cluster stride in raw
    if (idx >= total) return;

    float y[NC];
    float sum = 0.f, ssq = 0.f;
    {
        const float* p = raw + idx;
        #pragma unroll
        for (int c = 0; c < NC; ++c) {
            float t = log1p_fast(__ldg(p) * s_inv[c]);
            p += total;
            y[c] = t;
            sum += t;
            ssq = fmaf(t, t, ssq);
        }
    }

    const float meanY = sum / (float)NC;
    const float var = (ssq - sum * meanY) / (float)(NC - 1);
    const float idn = 1.f / (sqrtf(fmaxf(var, 0.f)) + 1e-5f);

    const int v = idx >> 6;
    const int d = idx & 63;
    float* o = out + (size_t)v * (2 * DIM) + d;   // (c*nv + v)*128 + d
    const size_t ostride = (size_t)n_variants * (2 * DIM);
    #pragma unroll
    for (int c = 0; c < NC; ++c) {
        __stcs(o, y[c] - 2.0f);
        __stcs(o + DIM, (y[c] - meanY) * idn);
        o += ostride;
    }
}

// Generic fallback (R6-proven two-pass form) for n_clusters != 50.
__global__ void __launch_bounds__(128) finalize_gen_kernel(
    const float* __restrict__ raw,
    const float* __restrict__ lib,
    float* __restrict__ out,
    int n_clusters, int n_variants)
{
    __shared__ float s_inv[MAX_CLUSTERS];
    if (threadIdx.x < n_clusters && threadIdx.x < MAX_CLUSTERS)
        s_inv[threadIdx.x] = 1.f / lib[threadIdx.x];
    __syncthreads();

    const int idx = blockIdx.x * blockDim.x + threadIdx.x;
    const int total = n_variants * DIM;
    if (idx >= total) return;

    const float* p = raw + idx;
    float sum = 0.f, ssq = 0.f;
    for (int c = 0; c < n_clusters; ++c) {
        float yv = log1p_fast(__ldg(p) * s_inv[c]);
        p += total;
        sum += yv;
        ssq = fmaf(yv, yv, ssq);
    }
    const float meanY = sum / (float)n_clusters;
    const float var = (ssq - sum * meanY) / (float)(n_clusters - 1);
    const float idn = 1.f / (sqrtf(fmaxf(var, 0.f)) + 1e-5f);

    const int v = idx >> 6;
    const int d = idx & 63;
    const float* p2 = raw + idx;
    float* o = out + (size_t)v * (2 * DIM) + d;
    const size_t ostride = (size_t)n_variants * (2 * DIM);
    for (int c = 0; c < n_clusters; ++c) {
        float yv = log1p_fast(__ldg(p2) * s_inv[c]);
        p2 += total;
        o[0]   = yv - 2.0f;
        o[DIM] = (yv - meanY) * idn;
        o += ostride;
    }
}

extern "C" void kernel_launch(void* const* d_in, const int* in_sizes, int n_in,
                              void* d_out, int out_size)
{
    const float* emb    = (const float*)d_in[0];   // [n_cuts, 64] fp32
    const float* lib    = (const float*)d_in[1];   // [n_clusters] fp32
    const int*   indptr = (const int*)d_in[2];     // [n_seg + 1] int32 OR int64 words

    const int n_clusters = in_sizes[1];
    const int n_seg      = in_sizes[2] - 1;
    const int n_variants = n_seg / n_clusters;

    float* raw;
    cudaGetSymbolAddress((void**)&raw, g_raw);

    // Kernel 1: one block per segment
    seg_sum_kernel<<<n_seg, 128>>>((const float4*)emb, indptr, raw);

    // Kernel 2: fused stats+apply, one thread per (variant, dim), 128-thr blocks
    const int total_vd = n_variants * DIM;
    const int blocks2 = (total_vd + 127) / 128;
    if (n_clusters == 50) {
        finalize_reg_kernel<50><<<blocks2, 128>>>(raw, lib, (float*)d_out,
                                                  n_variants);
    } else {
        finalize_gen_kernel<<<blocks2, 128>>>(raw, lib, (float*)d_out,
                                              n_clusters, n_variants);
    }
}